// round 1
// baseline (speedup 1.0000x reference)
#include <cuda_runtime.h>
#include <math.h>

namespace {

constexpr int CDIM = 512;   // feature dim
constexpr int MDIM = 512;   // number of memory slots
constexpr int TB   = 32;    // rows per block
constexpr int NT   = 512;   // threads per block

// smem: s_k[TB*C] | s_sc[TB*C] | s_keys[16*M] | s_inv[TB] | s_acc[3(+pad)]
constexpr int SMEM_FLOATS = TB * CDIM * 2 + 16 * MDIM + TB + 16;
constexpr int SMEM_BYTES  = SMEM_FLOATS * 4;

__global__ void zero_scalars_kernel(float* scalars) {
    if (threadIdx.x < 3) scalars[threadIdx.x] = 0.0f;
}

__global__ __launch_bounds__(NT, 1)
void memory_module_kernel(const float* __restrict__ key,
                          const float* __restrict__ query,
                          const float* __restrict__ keys,
                          const float* __restrict__ values,
                          float* __restrict__ out_read,
                          float* __restrict__ out_scalars) {
    extern __shared__ float smem[];
    float* s_k    = smem;                 // TB*CDIM   (normalized k; reused for values staging)
    float* s_sc   = smem + TB * CDIM;     // TB*CDIM   (score -> exp(s-max))
    float* s_keys = s_sc + TB * CDIM;     // 16*MDIM   (keys staging, layout [cc][m])
    float* s_inv  = s_keys + 16 * MDIM;   // TB        (1/Z1 per row)
    float* s_acc  = s_inv + TB;           // 3         (ent, gat, con partials)

    const int tid  = threadIdx.x;
    const int lane = tid & 31;
    const int warp = tid >> 5;            // 0..15
    const int tx   = tid & 63;            // 0..63 -> m block
    const int ty   = tid >> 6;            // 0..7  -> row block
    const int tx8  = tx * 8;
    const int ty4  = ty * 4;
    const long long t0 = (long long)blockIdx.x * TB;

    if (tid < 3) s_acc[tid] = 0.0f;

    // ---------------- Phase A: L2-normalize key rows into s_k ----------------
    #pragma unroll
    for (int rr = 0; rr < 2; rr++) {
        const int r = warp * 2 + rr;
        const float4* kp = (const float4*)(key + (t0 + r) * CDIM);
        float4 v[4];
        float ss = 0.f;
        #pragma unroll
        for (int k2 = 0; k2 < 4; k2++) {
            v[k2] = kp[lane + 32 * k2];
            ss += v[k2].x * v[k2].x + v[k2].y * v[k2].y
                + v[k2].z * v[k2].z + v[k2].w * v[k2].w;
        }
        #pragma unroll
        for (int off = 16; off; off >>= 1) ss += __shfl_xor_sync(0xffffffffu, ss, off);
        const float inv = 1.0f / fmaxf(sqrtf(ss), 1e-12f);
        float4* dst = (float4*)(s_k + r * CDIM);
        #pragma unroll
        for (int k2 = 0; k2 < 4; k2++) {
            float4 o = v[k2];
            o.x *= inv; o.y *= inv; o.z *= inv; o.w *= inv;
            dst[lane + 32 * k2] = o;
        }
    }
    __syncthreads();

    // ---------------- Phase B: score[32][512] = k @ keys^T ----------------
    float acc[4][8];
    #pragma unroll
    for (int i = 0; i < 4; i++)
        #pragma unroll
        for (int j = 0; j < 8; j++) acc[i][j] = 0.f;

    for (int cs = 0; cs < CDIM; cs += 16) {
        // stage keys[:, cs..cs+15] transposed into s_keys[cc][m]
        for (int tsk = tid; tsk < 2048; tsk += NT) {
            const int m  = tsk & 511;
            const int c4 = (tsk >> 9) << 2;
            const float4 kv = *(const float4*)(keys + (size_t)m * CDIM + cs + c4);
            s_keys[(c4 + 0) * MDIM + m] = kv.x;
            s_keys[(c4 + 1) * MDIM + m] = kv.y;
            s_keys[(c4 + 2) * MDIM + m] = kv.z;
            s_keys[(c4 + 3) * MDIM + m] = kv.w;
        }
        __syncthreads();

        #pragma unroll
        for (int cc4 = 0; cc4 < 16; cc4 += 4) {
            float4 a[4];
            #pragma unroll
            for (int i = 0; i < 4; i++)
                a[i] = *(const float4*)(s_k + (ty4 + i) * CDIM + cs + cc4);
            #pragma unroll
            for (int q = 0; q < 4; q++) {
                const float4 b0 = *(const float4*)(s_keys + (cc4 + q) * MDIM + tx8);
                const float4 b1 = *(const float4*)(s_keys + (cc4 + q) * MDIM + tx8 + 4);
                #pragma unroll
                for (int i = 0; i < 4; i++) {
                    const float aq = (q == 0) ? a[i].x : (q == 1) ? a[i].y
                                   : (q == 2) ? a[i].z : a[i].w;
                    acc[i][0] += aq * b0.x; acc[i][1] += aq * b0.y;
                    acc[i][2] += aq * b0.z; acc[i][3] += aq * b0.w;
                    acc[i][4] += aq * b1.x; acc[i][5] += aq * b1.y;
                    acc[i][6] += aq * b1.z; acc[i][7] += aq * b1.w;
                }
            }
        }
        __syncthreads();
    }
    // write score tile
    #pragma unroll
    for (int i = 0; i < 4; i++) {
        float4* d = (float4*)(s_sc + (ty4 + i) * CDIM + tx8);
        d[0] = make_float4(acc[i][0], acc[i][1], acc[i][2], acc[i][3]);
        d[1] = make_float4(acc[i][4], acc[i][5], acc[i][6], acc[i][7]);
    }
    __syncthreads();

    // ---------------- Phase C: per-row reductions ----------------
    {
        float ent = 0.f, con = 0.f, gat = 0.f;
        #pragma unroll
        for (int rr = 0; rr < 2; rr++) {
            const int r = warp * 2 + rr;
            float* srow = s_sc + r * CDIM;

            // max + argmax
            float mx = -1e30f; int mi = 0;
            #pragma unroll
            for (int k2 = 0; k2 < 16; k2++) {
                const float v = srow[lane + 32 * k2];
                if (v > mx) { mx = v; mi = lane + 32 * k2; }
            }
            #pragma unroll
            for (int off = 16; off; off >>= 1) {
                const float v2 = __shfl_down_sync(0xffffffffu, mx, off);
                const int   i2 = __shfl_down_sync(0xffffffffu, mi, off);
                if (v2 > mx || (v2 == mx && i2 < mi)) { mx = v2; mi = i2; }
            }
            mx = __shfl_sync(0xffffffffu, mx, 0);
            mi = __shfl_sync(0xffffffffu, mi, 0);

            // exp pass: z1 = sum e, z2 = sum e^2 (= softmax @ temperature 0.5), sw = sum s*e
            float z1 = 0.f, z2 = 0.f, sw = 0.f;
            #pragma unroll
            for (int k2 = 0; k2 < 16; k2++) {
                const float s = srow[lane + 32 * k2];
                const float e = __expf(s - mx);
                z1 += e; z2 += e * e; sw += s * e;
                srow[lane + 32 * k2] = e;   // keep unnormalized weights for GEMM2
            }
            #pragma unroll
            for (int off = 16; off; off >>= 1) {
                z1 += __shfl_xor_sync(0xffffffffu, z1, off);
                z2 += __shfl_xor_sync(0xffffffffu, z2, off);
                sw += __shfl_xor_sync(0xffffffffu, sw, off);
            }
            if (lane == 0) s_inv[r] = 1.0f / z1;

            // q normalize + gathering vs values[argmax]
            const float4* qp = (const float4*)(query + (t0 + r) * CDIM);
            float4 qv[4];
            float ssq = 0.f;
            #pragma unroll
            for (int k2 = 0; k2 < 4; k2++) {
                qv[k2] = qp[lane + 32 * k2];
                ssq += qv[k2].x * qv[k2].x + qv[k2].y * qv[k2].y
                     + qv[k2].z * qv[k2].z + qv[k2].w * qv[k2].w;
            }
            #pragma unroll
            for (int off = 16; off; off >>= 1) ssq += __shfl_xor_sync(0xffffffffu, ssq, off);
            const float qi = 1.0f / fmaxf(sqrtf(ssq), 1e-12f);

            const float4* vp = (const float4*)(values + (size_t)mi * CDIM);
            float g = 0.f;
            #pragma unroll
            for (int k2 = 0; k2 < 4; k2++) {
                const float4 vv = vp[lane + 32 * k2];
                const float dx = qv[k2].x * qi - vv.x;
                const float dy = qv[k2].y * qi - vv.y;
                const float dz = qv[k2].z * qi - vv.z;
                const float dw = qv[k2].w * qi - vv.w;
                g += dx * dx + dy * dy + dz * dz + dw * dw;
            }
            #pragma unroll
            for (int off = 16; off; off >>= 1) g += __shfl_xor_sync(0xffffffffu, g, off);

            if (lane == 0) {
                // entropy_row = -sum w log w = max + ln Z1 - (sum s*e)/Z1
                ent += mx + logf(z1) - sw / z1;
                // contrast: logp[idx] @ temp 0.5 = -ln Z2
                con += logf(z2);
                gat += g;
            }
        }
        if (lane == 0) {
            atomicAdd(&s_acc[0], ent);
            atomicAdd(&s_acc[1], gat);
            atomicAdd(&s_acc[2], con);
        }
    }
    __syncthreads();
    if (tid == 0) {
        atomicAdd(out_scalars + 0, s_acc[0] * (1.0f / 32768.0f));              // entropy mean
        atomicAdd(out_scalars + 1, s_acc[1] * (1.0f / (32768.0f * 512.0f)));   // gathering mean
        atomicAdd(out_scalars + 2, s_acc[2] * (1.0f / 12800.0f));              // contrast
    }

    // ---------------- Phase D: read = softmax(score) @ values ----------------
    float racc[4][8];
    #pragma unroll
    for (int i = 0; i < 4; i++)
        #pragma unroll
        for (int j = 0; j < 8; j++) racc[i][j] = 0.f;

    for (int ms = 0; ms < MDIM; ms += 32) {
        // stage values[ms..ms+31][:] into s_k (linear, coalesced)
        const float4* vsrc = (const float4*)(values + (size_t)ms * CDIM);
        float4* vdst = (float4*)s_k;
        for (int tsk = tid; tsk < (32 * CDIM) / 4; tsk += NT) vdst[tsk] = vsrc[tsk];
        __syncthreads();

        #pragma unroll
        for (int mm4 = 0; mm4 < 32; mm4 += 4) {
            float4 wv[4];
            #pragma unroll
            for (int i = 0; i < 4; i++)
                wv[i] = *(const float4*)(s_sc + (ty4 + i) * CDIM + ms + mm4);
            #pragma unroll
            for (int q = 0; q < 4; q++) {
                const float4 b0 = *(const float4*)(s_k + (mm4 + q) * CDIM + tx8);
                const float4 b1 = *(const float4*)(s_k + (mm4 + q) * CDIM + tx8 + 4);
                #pragma unroll
                for (int i = 0; i < 4; i++) {
                    const float wq = (q == 0) ? wv[i].x : (q == 1) ? wv[i].y
                                   : (q == 2) ? wv[i].z : wv[i].w;
                    racc[i][0] += wq * b0.x; racc[i][1] += wq * b0.y;
                    racc[i][2] += wq * b0.z; racc[i][3] += wq * b0.w;
                    racc[i][4] += wq * b1.x; racc[i][5] += wq * b1.y;
                    racc[i][6] += wq * b1.z; racc[i][7] += wq * b1.w;
                }
            }
        }
        __syncthreads();
    }

    // epilogue: scale by 1/Z1, store
    #pragma unroll
    for (int i = 0; i < 4; i++) {
        const float sc = s_inv[ty4 + i];
        float4* op = (float4*)(out_read + (t0 + ty4 + i) * CDIM + tx8);
        op[0] = make_float4(racc[i][0] * sc, racc[i][1] * sc, racc[i][2] * sc, racc[i][3] * sc);
        op[1] = make_float4(racc[i][4] * sc, racc[i][5] * sc, racc[i][6] * sc, racc[i][7] * sc);
    }
}

} // namespace

extern "C" void kernel_launch(void* const* d_in, const int* in_sizes, int n_in,
                              void* d_out, int out_size) {
    const float* key    = (const float*)d_in[0];
    const float* query  = (const float*)d_in[1];
    const float* keys   = (const float*)d_in[2];
    const float* values = (const float*)d_in[3];
    float* out = (float*)d_out;

    const size_t read_elems = (size_t)in_sizes[0];       // B*L*C
    const size_t keys_elems = (size_t)in_sizes[2];       // M*C
    const size_t vals_elems = (size_t)in_sizes[3];       // M*C
    const long long T = (long long)(read_elems / CDIM);  // 32768

    // output layout: read_query | entropy | gathering | contrast | keys | values
    float* out_scalars = out + read_elems;
    float* out_keys    = out + read_elems + 3;
    float* out_values  = out_keys + keys_elems;

    cudaMemcpyAsync(out_keys,   keys,   keys_elems * sizeof(float), cudaMemcpyDeviceToDevice, 0);
    cudaMemcpyAsync(out_values, values, vals_elems * sizeof(float), cudaMemcpyDeviceToDevice, 0);

    zero_scalars_kernel<<<1, 32, 0, 0>>>(out_scalars);

    static bool attr_set = false;
    if (!attr_set) {
        cudaFuncSetAttribute(memory_module_kernel,
                             cudaFuncAttributeMaxDynamicSharedMemorySize, SMEM_BYTES);
        attr_set = true;
    }

    const int grid = (int)(T / TB);   // 1024
    memory_module_kernel<<<grid, NT, SMEM_BYTES, 0>>>(key, query, keys, values,
                                                      out, out_scalars);
}

// round 4
// speedup vs baseline: 2.3392x; 2.3392x over previous
#include <cuda_runtime.h>
#include <math.h>

namespace {

constexpr int CDIM = 512;
constexpr int MDIM = 512;
constexpr int TB   = 32;
constexpr int NT   = 512;

// smem: s_k[TB*C] | s_sc[TB*C] | s_keys[32*M] | s_inv[TB] | s_acc[3(+pad)]
constexpr int SMEM_FLOATS = TB * CDIM * 2 + 32 * MDIM + TB + 16;
constexpr int SMEM_BYTES  = SMEM_FLOATS * 4;

typedef unsigned long long u64;

__device__ __forceinline__ u64 splat2(float x) {
    u64 r; asm("mov.b64 %0, {%1, %1};" : "=l"(r) : "f"(x)); return r;
}
__device__ __forceinline__ void ffma2(u64& d, u64 a, u64 b) {
    asm("fma.rn.f32x2 %0, %1, %2, %0;" : "+l"(d) : "l"(a), "l"(b));
}
__device__ __forceinline__ float2 unpack2(u64 v) {
    float2 r; asm("mov.b64 {%0, %1}, %2;" : "=f"(r.x), "=f"(r.y) : "l"(v)); return r;
}

__global__ void zero_scalars_kernel(float* scalars) {
    if (threadIdx.x < 3) scalars[threadIdx.x] = 0.0f;
}

__global__ __launch_bounds__(NT, 1)
void memory_module_kernel(const float* __restrict__ key,
                          const float* __restrict__ query,
                          const float* __restrict__ keys,
                          const float* __restrict__ values,
                          float* __restrict__ out_read,
                          float* __restrict__ out_scalars) {
    extern __shared__ float smem[];
    float* s_k    = smem;                 // TB*CDIM (normalized k; later: values staging)
    float* s_sc   = smem + TB * CDIM;     // TB*CDIM (score -> exp(s-max))
    float* s_keys = s_sc + TB * CDIM;     // 32*MDIM (keys staging, layout [c][m])
    float* s_inv  = s_keys + 32 * MDIM;   // TB
    float* s_acc  = s_inv + TB;           // 3

    const int tid  = threadIdx.x;
    const int lane = tid & 31;
    const int warp = tid >> 5;            // 0..15
    const int tx4  = (tid & 63) * 4;      // 0..252, column group
    const int ty4  = (tid >> 6) * 4;      // row group
    const long long t0 = (long long)blockIdx.x * TB;

    if (tid < 3) s_acc[tid] = 0.0f;

    // ---------------- Phase A: L2-normalize key rows into s_k ----------------
    #pragma unroll
    for (int rr = 0; rr < 2; rr++) {
        const int r = warp * 2 + rr;
        const float4* kp = (const float4*)(key + (t0 + r) * CDIM);
        float4 v[4];
        float ss = 0.f;
        #pragma unroll
        for (int k2 = 0; k2 < 4; k2++) {
            v[k2] = kp[lane + 32 * k2];
            ss += v[k2].x * v[k2].x + v[k2].y * v[k2].y
                + v[k2].z * v[k2].z + v[k2].w * v[k2].w;
        }
        #pragma unroll
        for (int off = 16; off; off >>= 1) ss += __shfl_xor_sync(0xffffffffu, ss, off);
        const float inv = 1.0f / fmaxf(sqrtf(ss), 1e-12f);
        float4* dst = (float4*)(s_k + r * CDIM);
        #pragma unroll
        for (int k2 = 0; k2 < 4; k2++) {
            float4 o = v[k2];
            o.x *= inv; o.y *= inv; o.z *= inv; o.w *= inv;
            dst[lane + 32 * k2] = o;
        }
    }
    __syncthreads();

    // ---------------- Phase B: score[32][512] = k @ keys^T (f32x2) ----------------
    // Thread owns rows ty4..ty4+3, columns {tx4..tx4+3} and {256+tx4..256+tx4+3}.
    u64 acc[4][4];
    #pragma unroll
    for (int i = 0; i < 4; i++)
        #pragma unroll
        for (int j = 0; j < 4; j++) acc[i][j] = 0ull;

    for (int cs = 0; cs < CDIM; cs += 32) {
        // stage keys[:, cs..cs+31] transposed into s_keys[c][m] (conflict-free)
        for (int t = tid; t < 4096; t += NT) {
            const int m  = t & 511;
            const int c4 = (t >> 9) << 2;
            const float4 kv = *(const float4*)(keys + (size_t)m * CDIM + cs + c4);
            s_keys[(c4 + 0) * MDIM + m] = kv.x;
            s_keys[(c4 + 1) * MDIM + m] = kv.y;
            s_keys[(c4 + 2) * MDIM + m] = kv.z;
            s_keys[(c4 + 3) * MDIM + m] = kv.w;
        }
        __syncthreads();

        #pragma unroll 4
        for (int cc = 0; cc < 32; cc += 4) {
            float a_[4][4];
            #pragma unroll
            for (int i = 0; i < 4; i++) {
                const float4 av = *(const float4*)(s_k + (ty4 + i) * CDIM + cs + cc);
                a_[i][0] = av.x; a_[i][1] = av.y; a_[i][2] = av.z; a_[i][3] = av.w;
            }
            #pragma unroll
            for (int q = 0; q < 4; q++) {
                const float* bp = s_keys + (cc + q) * MDIM;
                const ulonglong2 b0 = *(const ulonglong2*)(bp + tx4);         // lanes contiguous
                const ulonglong2 b1 = *(const ulonglong2*)(bp + 256 + tx4);
                #pragma unroll
                for (int i = 0; i < 4; i++) {
                    const u64 pa = splat2(a_[i][q]);
                    ffma2(acc[i][0], pa, b0.x);
                    ffma2(acc[i][1], pa, b0.y);
                    ffma2(acc[i][2], pa, b1.x);
                    ffma2(acc[i][3], pa, b1.y);
                }
            }
        }
        __syncthreads();
    }
    // write score tile
    #pragma unroll
    for (int i = 0; i < 4; i++) {
        ulonglong2* d0 = (ulonglong2*)(s_sc + (ty4 + i) * CDIM + tx4);
        ulonglong2* d1 = (ulonglong2*)(s_sc + (ty4 + i) * CDIM + 256 + tx4);
        *d0 = make_ulonglong2(acc[i][0], acc[i][1]);
        *d1 = make_ulonglong2(acc[i][2], acc[i][3]);
    }
    __syncthreads();

    // ---------------- Phase C: per-row reductions ----------------
    {
        float ent = 0.f, con = 0.f, gat = 0.f;
        #pragma unroll
        for (int rr = 0; rr < 2; rr++) {
            const int r = warp * 2 + rr;
            float* srow = s_sc + r * CDIM;

            float mx = -1e30f; int mi = 0;
            #pragma unroll
            for (int k2 = 0; k2 < 16; k2++) {
                const float v = srow[lane + 32 * k2];
                if (v > mx) { mx = v; mi = lane + 32 * k2; }
            }
            #pragma unroll
            for (int off = 16; off; off >>= 1) {
                const float v2 = __shfl_down_sync(0xffffffffu, mx, off);
                const int   i2 = __shfl_down_sync(0xffffffffu, mi, off);
                if (v2 > mx || (v2 == mx && i2 < mi)) { mx = v2; mi = i2; }
            }
            mx = __shfl_sync(0xffffffffu, mx, 0);
            mi = __shfl_sync(0xffffffffu, mi, 0);

            float z1 = 0.f, z2 = 0.f, sw = 0.f;
            #pragma unroll
            for (int k2 = 0; k2 < 16; k2++) {
                const float s = srow[lane + 32 * k2];
                const float e = __expf(s - mx);
                z1 += e; z2 += e * e; sw += s * e;
                srow[lane + 32 * k2] = e;
            }
            #pragma unroll
            for (int off = 16; off; off >>= 1) {
                z1 += __shfl_xor_sync(0xffffffffu, z1, off);
                z2 += __shfl_xor_sync(0xffffffffu, z2, off);
                sw += __shfl_xor_sync(0xffffffffu, sw, off);
            }
            if (lane == 0) s_inv[r] = 1.0f / z1;

            const float4* qp = (const float4*)(query + (t0 + r) * CDIM);
            float4 qv[4];
            float ssq = 0.f;
            #pragma unroll
            for (int k2 = 0; k2 < 4; k2++) {
                qv[k2] = qp[lane + 32 * k2];
                ssq += qv[k2].x * qv[k2].x + qv[k2].y * qv[k2].y
                     + qv[k2].z * qv[k2].z + qv[k2].w * qv[k2].w;
            }
            #pragma unroll
            for (int off = 16; off; off >>= 1) ssq += __shfl_xor_sync(0xffffffffu, ssq, off);
            const float qi = 1.0f / fmaxf(sqrtf(ssq), 1e-12f);

            const float4* vp = (const float4*)(values + (size_t)mi * CDIM);
            float g = 0.f;
            #pragma unroll
            for (int k2 = 0; k2 < 4; k2++) {
                const float4 vv = vp[lane + 32 * k2];
                const float dx = qv[k2].x * qi - vv.x;
                const float dy = qv[k2].y * qi - vv.y;
                const float dz = qv[k2].z * qi - vv.z;
                const float dw = qv[k2].w * qi - vv.w;
                g += dx * dx + dy * dy + dz * dz + dw * dw;
            }
            #pragma unroll
            for (int off = 16; off; off >>= 1) g += __shfl_xor_sync(0xffffffffu, g, off);

            if (lane == 0) {
                ent += mx + logf(z1) - sw / z1;
                con += logf(z2);
                gat += g;
            }
        }
        if (lane == 0) {
            atomicAdd(&s_acc[0], ent);
            atomicAdd(&s_acc[1], gat);
            atomicAdd(&s_acc[2], con);
        }
    }
    __syncthreads();
    if (tid == 0) {
        atomicAdd(out_scalars + 0, s_acc[0] * (1.0f / 32768.0f));
        atomicAdd(out_scalars + 1, s_acc[1] * (1.0f / (32768.0f * 512.0f)));
        atomicAdd(out_scalars + 2, s_acc[2] * (1.0f / 12800.0f));
    }

    // ---------------- Phase D: read = softmax(score) @ values (f32x2) ----------------
    u64 racc[4][4];
    #pragma unroll
    for (int i = 0; i < 4; i++)
        #pragma unroll
        for (int j = 0; j < 4; j++) racc[i][j] = 0ull;

    for (int ms = 0; ms < MDIM; ms += 32) {
        const float4* vsrc = (const float4*)(values + (size_t)ms * CDIM);
        float4* vdst = (float4*)s_k;
        for (int t = tid; t < (32 * CDIM) / 4; t += NT) vdst[t] = vsrc[t];
        __syncthreads();

        #pragma unroll 4
        for (int mm = 0; mm < 32; mm += 4) {
            float w_[4][4];
            #pragma unroll
            for (int i = 0; i < 4; i++) {
                const float4 wv = *(const float4*)(s_sc + (ty4 + i) * CDIM + ms + mm);
                w_[i][0] = wv.x; w_[i][1] = wv.y; w_[i][2] = wv.z; w_[i][3] = wv.w;
            }
            #pragma unroll
            for (int q = 0; q < 4; q++) {
                const float* bp = s_k + (mm + q) * CDIM;
                const ulonglong2 b0 = *(const ulonglong2*)(bp + tx4);
                const ulonglong2 b1 = *(const ulonglong2*)(bp + 256 + tx4);
                #pragma unroll
                for (int i = 0; i < 4; i++) {
                    const u64 pw = splat2(w_[i][q]);
                    ffma2(racc[i][0], pw, b0.x);
                    ffma2(racc[i][1], pw, b0.y);
                    ffma2(racc[i][2], pw, b1.x);
                    ffma2(racc[i][3], pw, b1.y);
                }
            }
        }
        __syncthreads();
    }

    // epilogue: scale by 1/Z1, store
    #pragma unroll
    for (int i = 0; i < 4; i++) {
        const float sc = s_inv[ty4 + i];
        float* orow = out_read + (t0 + ty4 + i) * CDIM;
        const float2 p0 = unpack2(racc[i][0]);
        const float2 p1 = unpack2(racc[i][1]);
        const float2 p2 = unpack2(racc[i][2]);
        const float2 p3 = unpack2(racc[i][3]);
        *(float4*)(orow + tx4)       = make_float4(p0.x * sc, p0.y * sc, p1.x * sc, p1.y * sc);
        *(float4*)(orow + 256 + tx4) = make_float4(p2.x * sc, p2.y * sc, p3.x * sc, p3.y * sc);
    }
}

} // namespace

extern "C" void kernel_launch(void* const* d_in, const int* in_sizes, int n_in,
                              void* d_out, int out_size) {
    const float* key    = (const float*)d_in[0];
    const float* query  = (const float*)d_in[1];
    const float* keys   = (const float*)d_in[2];
    const float* values = (const float*)d_in[3];
    float* out = (float*)d_out;

    const size_t read_elems = (size_t)in_sizes[0];
    const size_t keys_elems = (size_t)in_sizes[2];
    const size_t vals_elems = (size_t)in_sizes[3];
    const long long T = (long long)(read_elems / CDIM);

    float* out_scalars = out + read_elems;
    float* out_keys    = out + read_elems + 3;
    float* out_values  = out_keys + keys_elems;

    cudaMemcpyAsync(out_keys,   keys,   keys_elems * sizeof(float), cudaMemcpyDeviceToDevice, 0);
    cudaMemcpyAsync(out_values, values, vals_elems * sizeof(float), cudaMemcpyDeviceToDevice, 0);

    zero_scalars_kernel<<<1, 32, 0, 0>>>(out_scalars);

    static bool attr_set = false;
    if (!attr_set) {
        cudaFuncSetAttribute(memory_module_kernel,
                             cudaFuncAttributeMaxDynamicSharedMemorySize, SMEM_BYTES);
        attr_set = true;
    }

    const int grid = (int)(T / TB);
    memory_module_kernel<<<grid, NT, SMEM_BYTES, 0>>>(key, query, keys, values,
                                                      out, out_scalars);
}